// round 1
// baseline (speedup 1.0000x reference)
#include <cuda_runtime.h>

#define N_NODES 10000
#define N_EDGES 160000
#define BATCH   2
#define CIN     16
#define CHID    32
#define TT      8
#define NCLASS  23
#define KW      (N_NODES - NCLASS + 1)   // 9978
#define CHROW   256                      // B*T*CIN per node row
#define EPS     1e-5f

// ---------------- scratch (static __device__: no allocations) ----------------
__device__ float g_xt[N_NODES * CHROW];     // node-major features [n][bt*16+c]
__device__ float g_agg1[N_NODES * CHROW];   // first aggregation
__device__ float g_s[N_NODES * 16];         // s = h1 @ W2 per (n, bt)
__device__ int   g_deg[N_NODES];
__device__ int   g_cur[N_NODES];
__device__ int   g_rowptr[N_NODES + 1];
__device__ int   g_col[N_EDGES];
__device__ float g_v[BATCH * N_NODES];      // after tconv1
__device__ float g_z[BATCH * N_NODES];      // after LN2

// ---------------- f32x2 helpers ----------------
__device__ __forceinline__ unsigned long long pack2(float lo, float hi) {
    unsigned long long r;
    asm("mov.b64 %0, {%1, %2};" : "=l"(r) : "f"(lo), "f"(hi));
    return r;
}
__device__ __forceinline__ void unpack2(unsigned long long v, float& lo, float& hi) {
    asm("mov.b64 {%0, %1}, %2;" : "=f"(lo), "=f"(hi) : "l"(v));
}
__device__ __forceinline__ unsigned long long fma2(unsigned long long a,
                                                   unsigned long long b,
                                                   unsigned long long c) {
    unsigned long long d;
    asm("fma.rn.f32x2 %0, %1, %2, %3;" : "=l"(d) : "l"(a), "l"(b), "l"(c));
    return d;
}

// ---------------- kernels ----------------

// [B,CIN,T,N] -> [N, 256] with channel index (b*8+t)*16+c
__global__ void k_transpose(const float* __restrict__ feat) {
    __shared__ float tile[32 * 257];
    int n0 = blockIdx.x * 32;
    int tid = threadIdx.x;   // 256
    #pragma unroll 4
    for (int k = 0; k < 32; k++) {
        int i  = tid + k * 256;
        int ch = i >> 5;          // 0..255
        int nn = i & 31;
        int n  = n0 + nn;
        int c  = ch & 15;
        int bt = ch >> 4;
        int t  = bt & 7;
        int b  = bt >> 3;
        float val = 0.f;
        if (n < N_NODES)
            val = feat[(((b * CIN + c) * TT + t) * N_NODES) + n];
        tile[nn * 257 + ch] = val;
    }
    __syncthreads();
    for (int r = 0; r < 32; r++) {
        int n = n0 + r;
        if (n < N_NODES) g_xt[n * CHROW + tid] = tile[r * 257 + tid];
    }
}

__global__ void k_zero2() {
    int i = blockIdx.x * blockDim.x + threadIdx.x;
    if (i < N_NODES) { g_deg[i] = 0; g_cur[i] = 0; }
}

__global__ void k_hist(const int* __restrict__ dst) {
    int e = blockIdx.x * blockDim.x + threadIdx.x;
    if (e < N_EDGES) atomicAdd(&g_deg[dst[e]], 1);
}

__global__ void k_scan() {
    __shared__ int part[1024];
    int tid = threadIdx.x;
    const int CHK = 10;  // 1024*10 >= 10000
    int local[CHK];
    int base = tid * CHK;
    int sum = 0;
    #pragma unroll
    for (int i = 0; i < CHK; i++) {
        int idx = base + i;
        int d = (idx < N_NODES) ? g_deg[idx] : 0;
        local[i] = d;
        sum += d;
    }
    part[tid] = sum;
    __syncthreads();
    for (int off = 1; off < 1024; off <<= 1) {
        int v = (tid >= off) ? part[tid - off] : 0;
        __syncthreads();
        part[tid] += v;
        __syncthreads();
    }
    int run = (tid > 0) ? part[tid - 1] : 0;
    #pragma unroll
    for (int i = 0; i < CHK; i++) {
        int idx = base + i;
        if (idx < N_NODES) g_rowptr[idx] = run;
        run += local[i];
    }
    if (tid == 1023) g_rowptr[N_NODES] = run;
}

__global__ void k_fill(const int* __restrict__ src, const int* __restrict__ dst) {
    int e = blockIdx.x * blockDim.x + threadIdx.x;
    if (e < N_EDGES) {
        int d = dst[e];
        int p = g_rowptr[d] + atomicAdd(&g_cur[d], 1);
        g_col[p] = src[e];
    }
}

// agg1: warp per node, lane owns 8 channels (2 float4), gather 1KB row per edge
__global__ void k_agg1() {
    int gt = blockIdx.x * blockDim.x + threadIdx.x;  // grid exact: 1250*256 = 320000 = N*32
    int n = gt >> 5;
    int lane = gt & 31;
    int beg = g_rowptr[n], end = g_rowptr[n + 1];
    float4 a0 = make_float4(0.f, 0.f, 0.f, 0.f);
    float4 a1 = make_float4(0.f, 0.f, 0.f, 0.f);
    const float4* base = reinterpret_cast<const float4*>(g_xt);
    int off = lane * 2;  // float4 units within 64-float4 row
    for (int e = beg; e < end; e++) {
        int s = g_col[e];
        const float4* p = base + s * 64 + off;
        float4 x0 = p[0], x1 = p[1];
        a0.x += x0.x; a0.y += x0.y; a0.z += x0.z; a0.w += x0.w;
        a1.x += x1.x; a1.y += x1.y; a1.z += x1.z; a1.w += x1.w;
    }
    float4* outp = reinterpret_cast<float4*>(g_agg1) + n * 64 + off;
    outp[0] = a0;
    outp[1] = a1;
}

// s[n][bt] = relu(agg1[n][bt] @ W1 + b1) @ W2 ; two t's per thread via f32x2
__global__ void __launch_bounds__(128) k_mlp(const float* __restrict__ W1,
                                             const float* __restrict__ b1,
                                             const float* __restrict__ W2) {
    __shared__ unsigned long long w1p[CIN * CHID];
    __shared__ float sb1[CHID], sw2[CHID];
    int tid = threadIdx.x;
    for (int i = tid; i < CIN * CHID; i += 128) {
        float w = W1[i];
        w1p[i] = pack2(w, w);
    }
    if (tid < CHID) { sb1[tid] = b1[tid]; sw2[tid] = W2[tid]; }
    __syncthreads();

    int idx = blockIdx.x * 128 + tid;   // grid exact: 625*128 = 80000 = N*8
    int n  = idx >> 3;
    int r  = idx & 7;
    int b  = r >> 2;
    int tp = r & 3;   // t-pair: t0 = 2*tp, t1 = 2*tp+1

    const float* row = g_agg1 + n * CHROW + (b * TT + tp * 2) * CIN;
    unsigned long long a[CIN];
    #pragma unroll
    for (int c = 0; c < CIN; c++) a[c] = pack2(row[c], row[c + CIN]);

    unsigned long long acc[CHID];
    #pragma unroll
    for (int j = 0; j < CHID; j++) acc[j] = pack2(sb1[j], sb1[j]);

    #pragma unroll
    for (int c = 0; c < CIN; c++) {
        #pragma unroll
        for (int j = 0; j < CHID; j++)
            acc[j] = fma2(a[c], w1p[c * CHID + j], acc[j]);
    }

    float s0 = 0.f, s1 = 0.f;
    #pragma unroll
    for (int j = 0; j < CHID; j++) {
        float lo, hi;
        unpack2(acc[j], lo, hi);
        s0 = fmaf(fmaxf(lo, 0.f), sw2[j], s0);
        s1 = fmaf(fmaxf(hi, 0.f), sw2[j], s1);
    }
    int sbase = n * 16 + b * TT + tp * 2;
    g_s[sbase]     = s0;
    g_s[sbase + 1] = s1;
}

// agg2 (16 floats/edge) + b2 + tconv1 contraction over t -> v[b][n]
__global__ void k_agg2(const float* __restrict__ b2,
                       const float* __restrict__ tw1,
                       const float* __restrict__ tb1) {
    int gt = blockIdx.x * blockDim.x + threadIdx.x;  // grid exact: 1250*128 = 160000 = N*16
    int n = gt >> 4;
    int l = gt & 15;
    int beg = g_rowptr[n], end = g_rowptr[n + 1];
    float acc = 0.f;
    for (int e = beg; e < end; e++)
        acc += g_s[g_col[e] * 16 + l];
    int b = l >> 3;
    int t = l & 7;
    float val = (acc + b2[0]) * tw1[t];
    val += __shfl_down_sync(0xffffffffu, val, 4);
    val += __shfl_down_sync(0xffffffffu, val, 2);
    val += __shfl_down_sync(0xffffffffu, val, 1);
    if (t == 0) g_v[b * N_NODES + n] = val + tb1[0];
}

__device__ float block_reduce_sum(float val, float* red) {
    int tid = threadIdx.x;
    red[tid] = val;
    __syncthreads();
    for (int off = 512; off > 0; off >>= 1) {
        if (tid < off) red[tid] += red[tid + off];
        __syncthreads();
    }
    float r = red[0];
    __syncthreads();
    return r;
}

// LN1 -> tconv2 affine -> LN2 (exact same numerics as reference)
__global__ void k_ln(const float* __restrict__ ln1g, const float* __restrict__ ln1b,
                     const float* __restrict__ tw2,  const float* __restrict__ tb2,
                     const float* __restrict__ ln2g, const float* __restrict__ ln2b) {
    __shared__ float red[1024];
    int tid = threadIdx.x;
    float w2v = tw2[0], bb2 = tb2[0];
    for (int b = 0; b < BATCH; b++) {
        const float* v = g_v + b * N_NODES;
        float s = 0.f;
        for (int i = tid; i < N_NODES; i += 1024) s += v[i];
        float mu1 = block_reduce_sum(s, red) * (1.f / N_NODES);
        s = 0.f;
        for (int i = tid; i < N_NODES; i += 1024) { float d = v[i] - mu1; s += d * d; }
        float inv1 = rsqrtf(block_reduce_sum(s, red) * (1.f / N_NODES) + EPS);
        s = 0.f;
        for (int i = tid; i < N_NODES; i += 1024) {
            float y = (v[i] - mu1) * inv1 * ln1g[i] + ln1b[i];
            s += y * w2v + bb2;
        }
        float mu2 = block_reduce_sum(s, red) * (1.f / N_NODES);
        s = 0.f;
        for (int i = tid; i < N_NODES; i += 1024) {
            float y  = (v[i] - mu1) * inv1 * ln1g[i] + ln1b[i];
            float y2 = y * w2v + bb2;
            float d  = y2 - mu2;
            s += d * d;
        }
        float inv2 = rsqrtf(block_reduce_sum(s, red) * (1.f / N_NODES) + EPS);
        for (int i = tid; i < N_NODES; i += 1024) {
            float y  = (v[i] - mu1) * inv1 * ln1g[i] + ln1b[i];
            float y2 = y * w2v + bb2;
            g_z[b * N_NODES + i] = (y2 - mu2) * inv2 * ln2g[i] + ln2b[i];
        }
        __syncthreads();
    }
}

// final conv over node dim: out[b][c] = sum_k z[b][c+k]*fc_w[k] + fc_b
__global__ void k_fc(const float* __restrict__ fc_w,
                     const float* __restrict__ fc_b,
                     float* __restrict__ out) {
    __shared__ float red[256];
    int c = blockIdx.x;   // 0..22
    int b = blockIdx.y;   // 0..1
    int tid = threadIdx.x;
    const float* z = g_z + b * N_NODES + c;
    float s = 0.f;
    for (int k = tid; k < KW; k += 256) s = fmaf(z[k], fc_w[k], s);
    red[tid] = s;
    __syncthreads();
    for (int off = 128; off > 0; off >>= 1) {
        if (tid < off) red[tid] += red[tid + off];
        __syncthreads();
    }
    if (tid == 0) out[b * NCLASS + c] = red[0] + fc_b[0];
}

// ---------------- launch ----------------
extern "C" void kernel_launch(void* const* d_in, const int* in_sizes, int n_in,
                              void* d_out, int out_size) {
    const float* features = (const float*)d_in[0];
    const int*   src      = (const int*)d_in[1];
    const int*   dst      = (const int*)d_in[2];
    const float* W1       = (const float*)d_in[3];
    const float* b1       = (const float*)d_in[4];
    const float* W2       = (const float*)d_in[5];
    const float* b2       = (const float*)d_in[6];
    const float* tconv1_w = (const float*)d_in[7];
    const float* tconv1_b = (const float*)d_in[8];
    const float* ln1_g    = (const float*)d_in[9];
    const float* ln1_b    = (const float*)d_in[10];
    const float* tconv2_w = (const float*)d_in[11];
    const float* tconv2_b = (const float*)d_in[12];
    const float* ln2_g    = (const float*)d_in[13];
    const float* ln2_b    = (const float*)d_in[14];
    const float* fc_w     = (const float*)d_in[15];
    const float* fc_b     = (const float*)d_in[16];
    float* out = (float*)d_out;

    k_zero2<<<(N_NODES + 255) / 256, 256>>>();
    k_hist<<<(N_EDGES + 255) / 256, 256>>>(dst);
    k_scan<<<1, 1024>>>();
    k_fill<<<(N_EDGES + 255) / 256, 256>>>(src, dst);
    k_transpose<<<(N_NODES + 31) / 32, 256>>>(features);
    k_agg1<<<(N_NODES * 32) / 256, 256>>>();
    k_mlp<<<(N_NODES * 8) / 128, 128>>>(W1, b1, W2);
    k_agg2<<<(N_NODES * 16) / 128, 128>>>(b2, tconv1_w, tconv1_b);
    k_ln<<<1, 1024>>>(ln1_g, ln1_b, tconv2_w, tconv2_b, ln2_g, ln2_b);
    k_fc<<<dim3(NCLASS, BATCH), 256>>>(fc_w, fc_b, out);
}

// round 2
// speedup vs baseline: 1.0808x; 1.0808x over previous
#include <cuda_runtime.h>
#include <cuda_fp16.h>

#define N_NODES 10000
#define N_EDGES 160000
#define BATCH   2
#define CIN     16
#define CHID    32
#define TT      8
#define NCLASS  23
#define KW      (N_NODES - NCLASS + 1)   // 9978
#define CHROW   256                      // B*T*CIN per node row
#define EPS     1e-5f

// ---------------- scratch (static __device__: no allocations) ----------------
__device__ __half g_xt[N_NODES * CHROW];    // node-major features fp16 [n][bt*16+c]
__device__ float  g_s[N_NODES * 16];        // s = relu(agg1@W1+b1)@W2 per (n, bt)
__device__ int    g_deg[N_NODES];           // zero-initialized; k_scan re-zeros it
__device__ int    g_cur[N_NODES];           // running cursor, seeded by k_scan
__device__ int    g_rowptr[N_NODES + 1];
__device__ int    g_col[N_EDGES];
__device__ float  g_v[BATCH * N_NODES];     // after tconv1

// ---------------- fused transpose + degree histogram ----------------
// blocks [0, 313): transpose [B,CIN,T,N] -> fp16 [N][256], ch = (b*8+t)*16+c
// blocks [313, 938): histogram of dst into g_deg (g_deg zeroed by prior k_scan)
__global__ void k_pre(const float* __restrict__ feat, const int* __restrict__ dst) {
    if (blockIdx.x < 313) {
        __shared__ float tile[32 * 257];
        int n0 = blockIdx.x * 32;
        int tid = threadIdx.x;   // 256
        #pragma unroll 4
        for (int k = 0; k < 32; k++) {
            int i  = tid + k * 256;
            int ch = i >> 5;          // 0..255
            int nn = i & 31;
            int n  = n0 + nn;
            int c  = ch & 15;
            int bt = ch >> 4;
            int t  = bt & 7;
            int b  = bt >> 3;
            float val = 0.f;
            if (n < N_NODES)
                val = feat[(((b * CIN + c) * TT + t) * N_NODES) + n];
            tile[nn * 257 + ch] = val;
        }
        __syncthreads();
        for (int r = 0; r < 32; r++) {
            int n = n0 + r;
            if (n < N_NODES)
                g_xt[n * CHROW + tid] = __float2half(tile[r * 257 + tid]);
        }
    } else {
        int e = (blockIdx.x - 313) * 256 + threadIdx.x;
        if (e < N_EDGES) atomicAdd(&g_deg[dst[e]], 1);
    }
}

// exclusive scan of g_deg -> g_rowptr; seed g_cur = rowptr; reset g_deg = 0
__global__ void k_scan() {
    __shared__ int part[1024];
    int tid = threadIdx.x;
    const int CHK = 10;  // 1024*10 >= 10001
    int local[CHK];
    int base = tid * CHK;
    int sum = 0;
    #pragma unroll
    for (int i = 0; i < CHK; i++) {
        int idx = base + i;
        int d = (idx < N_NODES) ? g_deg[idx] : 0;
        local[i] = d;
        sum += d;
    }
    part[tid] = sum;
    __syncthreads();
    for (int off = 1; off < 1024; off <<= 1) {
        int v = (tid >= off) ? part[tid - off] : 0;
        __syncthreads();
        part[tid] += v;
        __syncthreads();
    }
    int run = (tid > 0) ? part[tid - 1] : 0;
    #pragma unroll
    for (int i = 0; i < CHK; i++) {
        int idx = base + i;
        if (idx < N_NODES) {
            g_rowptr[idx] = run;
            g_cur[idx]    = run;
            g_deg[idx]    = 0;      // ready for next replay's histogram
        }
        run += local[i];
    }
    if (tid == 1023) g_rowptr[N_NODES] = run;
}

__global__ void k_fill(const int* __restrict__ src, const int* __restrict__ dst) {
    int e = blockIdx.x * blockDim.x + threadIdx.x;
    if (e < N_EDGES) {
        int d = dst[e];
        int p = atomicAdd(&g_cur[d], 1);
        g_col[p] = src[e];
    }
}

// ---------------- fused agg1 + MLP ----------------
// warp per node. Lane owns 8 fp16 channels (one uint4 = 16B of the 512B row).
// After gathering, lane pair (2k,2k+1) holds the 16 inputs of bt-slice k;
// exchange via shfl_xor, each lane computes 16 of the 32 hidden units,
// ReLU, dot with W2, pair-combine -> g_s[n][bt].
__global__ void __launch_bounds__(256) k_aggmlp(const float* __restrict__ W1,
                                                const float* __restrict__ b1,
                                                const float* __restrict__ W2) {
    __shared__ float sW1[CIN * CHID];
    __shared__ float sb1[CHID], sw2[CHID];
    int tid = threadIdx.x;
    #pragma unroll
    for (int i = tid; i < CIN * CHID; i += 256) sW1[i] = W1[i];
    if (tid < CHID) { sb1[tid] = b1[tid]; sw2[tid] = W2[tid]; }
    __syncthreads();

    int gt = blockIdx.x * 256 + tid;     // 1250 * 256 = 320000 = N * 32 exact
    int n = gt >> 5;
    int lane = gt & 31;
    int beg = g_rowptr[n], end = g_rowptr[n + 1];

    float a[8];
    #pragma unroll
    for (int i = 0; i < 8; i++) a[i] = 0.f;

    const uint4* base = reinterpret_cast<const uint4*>(g_xt);
    for (int e = beg; e < end; e++) {
        int s = g_col[e];
        uint4 v = base[s * 32 + lane];
        float2 f;
        f = __half22float2(*reinterpret_cast<__half2*>(&v.x)); a[0] += f.x; a[1] += f.y;
        f = __half22float2(*reinterpret_cast<__half2*>(&v.y)); a[2] += f.x; a[3] += f.y;
        f = __half22float2(*reinterpret_cast<__half2*>(&v.z)); a[4] += f.x; a[5] += f.y;
        f = __half22float2(*reinterpret_cast<__half2*>(&v.w)); a[6] += f.x; a[7] += f.y;
    }

    // exchange within lane pair to assemble all 16 inputs of this bt-slice
    int hi = lane & 1;           // 0: owns c0..7,  1: owns c8..15
    float x[16];
    #pragma unroll
    for (int i = 0; i < 8; i++) {
        float other = __shfl_xor_sync(0xffffffffu, a[i], 1);
        x[i]     = hi ? other : a[i];
        x[8 + i] = hi ? a[i]  : other;
    }

    int jb = hi ? 16 : 0;        // even lane: hidden 0..15, odd: 16..31
    float partial = 0.f;
    #pragma unroll
    for (int j = 0; j < 16; j++) {
        float acc = sb1[jb + j];
        #pragma unroll
        for (int c = 0; c < 16; c++)
            acc = fmaf(x[c], sW1[c * CHID + jb + j], acc);
        partial = fmaf(fmaxf(acc, 0.f), sw2[jb + j], partial);
    }
    partial += __shfl_xor_sync(0xffffffffu, partial, 1);
    if (!hi) g_s[n * 16 + (lane >> 1)] = partial;
}

// agg2 (16 floats/edge gather of g_s) + b2 + tconv1 over t -> g_v[b][n]
__global__ void k_agg2(const float* __restrict__ b2,
                       const float* __restrict__ tw1,
                       const float* __restrict__ tb1) {
    int gt = blockIdx.x * blockDim.x + threadIdx.x;  // 1250*128 = 160000 = N*16
    int n = gt >> 4;
    int l = gt & 15;
    int beg = g_rowptr[n], end = g_rowptr[n + 1];
    float acc = 0.f;
    for (int e = beg; e < end; e++)
        acc += g_s[g_col[e] * 16 + l];
    int b = l >> 3;
    int t = l & 7;
    float val = (acc + b2[0]) * tw1[t];
    val += __shfl_down_sync(0xffffffffu, val, 4);
    val += __shfl_down_sync(0xffffffffu, val, 2);
    val += __shfl_down_sync(0xffffffffu, val, 1);
    if (t == 0) g_v[b * N_NODES + n] = val + tb1[0];
}

__device__ __forceinline__ float block_reduce_sum(float val, float* red) {
    int tid = threadIdx.x;
    red[tid] = val;
    __syncthreads();
    for (int off = 512; off > 0; off >>= 1) {
        if (tid < off) red[tid] += red[tid + off];
        __syncthreads();
    }
    float r = red[0];
    __syncthreads();
    return r;
}

// fused LN1 -> tconv2 affine -> LN2 -> width-9978 fc conv. One block per batch.
__global__ void __launch_bounds__(1024) k_lnfc(
        const float* __restrict__ ln1g, const float* __restrict__ ln1b,
        const float* __restrict__ tw2,  const float* __restrict__ tb2,
        const float* __restrict__ ln2g, const float* __restrict__ ln2b,
        const float* __restrict__ fc_w, const float* __restrict__ fc_b,
        float* __restrict__ out) {
    __shared__ float z[N_NODES];          // 40000 B
    __shared__ float red[1024];           //  4096 B
    __shared__ float cred[32 * NCLASS];   //  2944 B
    int b = blockIdx.x;
    int tid = threadIdx.x;
    const float* v = g_v + b * N_NODES;
    float w2v = tw2[0], bb2 = tb2[0];

    float s = 0.f;
    for (int i = tid; i < N_NODES; i += 1024) s += v[i];
    float mu1 = block_reduce_sum(s, red) * (1.f / N_NODES);
    s = 0.f;
    for (int i = tid; i < N_NODES; i += 1024) { float d = v[i] - mu1; s += d * d; }
    float inv1 = rsqrtf(block_reduce_sum(s, red) * (1.f / N_NODES) + EPS);
    s = 0.f;
    for (int i = tid; i < N_NODES; i += 1024) {
        float y = (v[i] - mu1) * inv1 * ln1g[i] + ln1b[i];
        s += y * w2v + bb2;
    }
    float mu2 = block_reduce_sum(s, red) * (1.f / N_NODES);
    s = 0.f;
    for (int i = tid; i < N_NODES; i += 1024) {
        float y  = (v[i] - mu1) * inv1 * ln1g[i] + ln1b[i];
        float y2 = y * w2v + bb2;
        float d  = y2 - mu2;
        s += d * d;
    }
    float inv2 = rsqrtf(block_reduce_sum(s, red) * (1.f / N_NODES) + EPS);
    for (int i = tid; i < N_NODES; i += 1024) {
        float y  = (v[i] - mu1) * inv1 * ln1g[i] + ln1b[i];
        float y2 = y * w2v + bb2;
        z[i] = (y2 - mu2) * inv2 * ln2g[i] + ln2b[i];
    }
    __syncthreads();

    // fc: out[c] = sum_{k} z[c+k] * w[k]; each position p contributes w[p-c]
    float acc[NCLASS];
    #pragma unroll
    for (int c = 0; c < NCLASS; c++) acc[c] = 0.f;
    for (int p = tid; p < N_NODES; p += 1024) {
        float zv = z[p];
        #pragma unroll
        for (int c = 0; c < NCLASS; c++) {
            int k = p - c;
            if (k >= 0 && k < KW) acc[c] = fmaf(zv, fc_w[k], acc[c]);
        }
    }
    int lane = tid & 31, wrp = tid >> 5;
    #pragma unroll
    for (int c = 0; c < NCLASS; c++) {
        float a = acc[c];
        a += __shfl_down_sync(0xffffffffu, a, 16);
        a += __shfl_down_sync(0xffffffffu, a, 8);
        a += __shfl_down_sync(0xffffffffu, a, 4);
        a += __shfl_down_sync(0xffffffffu, a, 2);
        a += __shfl_down_sync(0xffffffffu, a, 1);
        if (lane == 0) cred[wrp * NCLASS + c] = a;
    }
    __syncthreads();
    if (tid < NCLASS) {
        float a = 0.f;
        #pragma unroll
        for (int w = 0; w < 32; w++) a += cred[w * NCLASS + tid];
        out[b * NCLASS + tid] = a + fc_b[0];
    }
}

// ---------------- launch ----------------
extern "C" void kernel_launch(void* const* d_in, const int* in_sizes, int n_in,
                              void* d_out, int out_size) {
    const float* features = (const float*)d_in[0];
    const int*   src      = (const int*)d_in[1];
    const int*   dst      = (const int*)d_in[2];
    const float* W1       = (const float*)d_in[3];
    const float* b1       = (const float*)d_in[4];
    const float* W2       = (const float*)d_in[5];
    const float* b2       = (const float*)d_in[6];
    const float* tconv1_w = (const float*)d_in[7];
    const float* tconv1_b = (const float*)d_in[8];
    const float* ln1_g    = (const float*)d_in[9];
    const float* ln1_b    = (const float*)d_in[10];
    const float* tconv2_w = (const float*)d_in[11];
    const float* tconv2_b = (const float*)d_in[12];
    const float* ln2_g    = (const float*)d_in[13];
    const float* ln2_b    = (const float*)d_in[14];
    const float* fc_w     = (const float*)d_in[15];
    const float* fc_b     = (const float*)d_in[16];
    float* out = (float*)d_out;

    k_pre<<<938, 256>>>(features, dst);           // transpose + degree hist
    k_scan<<<1, 1024>>>();                        // rowptr, cur, deg reset
    k_fill<<<625, 256>>>(src, dst);               // CSR column fill
    k_aggmlp<<<1250, 256>>>(W1, b1, W2);          // agg1 + MLP fused
    k_agg2<<<1250, 128>>>(b2, tconv1_w, tconv1_b);// agg2 + tconv1
    k_lnfc<<<BATCH, 1024>>>(ln1_g, ln1_b, tconv2_w, tconv2_b,
                            ln2_g, ln2_b, fc_w, fc_b, out);
}

// round 3
// speedup vs baseline: 1.2917x; 1.1951x over previous
#include <cuda_runtime.h>
#include <cuda_fp16.h>

#define N_NODES 10000
#define N_EDGES 160000
#define BATCH   2
#define CIN     16
#define CHID    32
#define TT      8
#define NCLASS  23
#define KW      (N_NODES - NCLASS + 1)   // 9978
#define CHROW   256
#define EPS     1e-5f

// ---------------- scratch ----------------
__device__ __half g_xt[N_NODES * CHROW];
__device__ float  g_s[N_NODES * 16];
__device__ int    g_deg[N_NODES];          // zero-init; k_scan re-zeros each call
__device__ int    g_cur[N_NODES];
__device__ int    g_rowptr[N_NODES + 1];
__device__ int    g_col[N_EDGES];
__device__ float  g_v[BATCH * N_NODES];
__device__ float  g_z[BATCH * N_NODES];

// ---------------- transpose + degree histogram (ILP=4 hist) ----------------
__global__ void k_pre(const float* __restrict__ feat, const int* __restrict__ dst) {
    if (blockIdx.x < 313) {
        __shared__ float tile[32 * 257];
        int n0 = blockIdx.x * 32;
        int tid = threadIdx.x;   // 256
        #pragma unroll 4
        for (int k = 0; k < 32; k++) {
            int i  = tid + k * 256;
            int ch = i >> 5;
            int nn = i & 31;
            int n  = n0 + nn;
            int c  = ch & 15;
            int bt = ch >> 4;
            int t  = bt & 7;
            int b  = bt >> 3;
            float val = 0.f;
            if (n < N_NODES)
                val = feat[(((b * CIN + c) * TT + t) * N_NODES) + n];
            tile[nn * 257 + ch] = val;
        }
        __syncthreads();
        for (int r = 0; r < 32; r++) {
            int n = n0 + r;
            if (n < N_NODES)
                g_xt[n * CHROW + tid] = __float2half(tile[r * 257 + tid]);
        }
    } else {
        int base = (blockIdx.x - 313) * 1024 + threadIdx.x;
        #pragma unroll
        for (int k = 0; k < 4; k++) {
            int e = base + k * 256;
            if (e < N_EDGES) atomicAdd(&g_deg[dst[e]], 1);
        }
    }
}

// exclusive scan via shfl (2 barriers); seed g_cur; reset g_deg
__global__ void __launch_bounds__(1024) k_scan() {
    __shared__ int wsum[32];
    int tid = threadIdx.x, lane = tid & 31, w = tid >> 5;
    const int CHK = 10;
    int local[CHK];
    int base = tid * CHK;
    int sum = 0;
    #pragma unroll
    for (int i = 0; i < CHK; i++) {
        int idx = base + i;
        int d = (idx < N_NODES) ? g_deg[idx] : 0;
        local[i] = d;
        sum += d;
    }
    int inc = sum;
    #pragma unroll
    for (int off = 1; off < 32; off <<= 1) {
        int u = __shfl_up_sync(0xffffffffu, inc, off);
        if (lane >= off) inc += u;
    }
    if (lane == 31) wsum[w] = inc;
    __syncthreads();
    if (w == 0) {
        int s = wsum[lane];
        #pragma unroll
        for (int off = 1; off < 32; off <<= 1) {
            int u = __shfl_up_sync(0xffffffffu, s, off);
            if (lane >= off) s += u;
        }
        wsum[lane] = s;
    }
    __syncthreads();
    int run = ((w > 0) ? wsum[w - 1] : 0) + (inc - sum);
    #pragma unroll
    for (int i = 0; i < CHK; i++) {
        int idx = base + i;
        if (idx < N_NODES) {
            g_rowptr[idx] = run;
            g_cur[idx]    = run;
            g_deg[idx]    = 0;
        }
        run += local[i];
    }
    if (tid == 1023) g_rowptr[N_NODES] = run;
}

// CSR column fill, ILP=4
__global__ void k_fill(const int* __restrict__ src, const int* __restrict__ dst) {
    int base = blockIdx.x * 1024 + threadIdx.x;
    #pragma unroll
    for (int k = 0; k < 4; k++) {
        int e = base + k * 256;
        if (e < N_EDGES) {
            int d = dst[e];
            int p = atomicAdd(&g_cur[d], 1);
            g_col[p] = src[e];
        }
    }
}

// ---------------- fused agg1 (fp16 acc) + MLP (LDS.128 weights) ----------------
__global__ void __launch_bounds__(256, 4) k_aggmlp(const float* __restrict__ W1,
                                                   const float* __restrict__ b1,
                                                   const float* __restrict__ W2) {
    __shared__ float sW1[CIN * CHID];    // [c][32]
    __shared__ float sb1[CHID], sw2[CHID];
    int tid = threadIdx.x;
    #pragma unroll
    for (int i = tid; i < CIN * CHID; i += 256) sW1[i] = W1[i];
    if (tid < CHID) { sb1[tid] = b1[tid]; sw2[tid] = W2[tid]; }
    __syncthreads();

    int gt = blockIdx.x * 256 + tid;     // 1250*256 = N*32 exact
    int n = gt >> 5;
    int lane = gt & 31;
    int beg = g_rowptr[n], end = g_rowptr[n + 1];

    __half2 h0[4], h1[4];
    #pragma unroll
    for (int k = 0; k < 4; k++) { h0[k] = __float2half2_rn(0.f); h1[k] = __float2half2_rn(0.f); }

    const uint4* basep = reinterpret_cast<const uint4*>(g_xt);
    int e = beg;
    for (; e + 1 < end; e += 2) {
        int s0 = g_col[e], s1 = g_col[e + 1];
        uint4 v0 = basep[s0 * 32 + lane];
        uint4 v1 = basep[s1 * 32 + lane];
        h0[0] = __hadd2(h0[0], *reinterpret_cast<__half2*>(&v0.x));
        h0[1] = __hadd2(h0[1], *reinterpret_cast<__half2*>(&v0.y));
        h0[2] = __hadd2(h0[2], *reinterpret_cast<__half2*>(&v0.z));
        h0[3] = __hadd2(h0[3], *reinterpret_cast<__half2*>(&v0.w));
        h1[0] = __hadd2(h1[0], *reinterpret_cast<__half2*>(&v1.x));
        h1[1] = __hadd2(h1[1], *reinterpret_cast<__half2*>(&v1.y));
        h1[2] = __hadd2(h1[2], *reinterpret_cast<__half2*>(&v1.z));
        h1[3] = __hadd2(h1[3], *reinterpret_cast<__half2*>(&v1.w));
    }
    if (e < end) {
        int s0 = g_col[e];
        uint4 v0 = basep[s0 * 32 + lane];
        h0[0] = __hadd2(h0[0], *reinterpret_cast<__half2*>(&v0.x));
        h0[1] = __hadd2(h0[1], *reinterpret_cast<__half2*>(&v0.y));
        h0[2] = __hadd2(h0[2], *reinterpret_cast<__half2*>(&v0.z));
        h0[3] = __hadd2(h0[3], *reinterpret_cast<__half2*>(&v0.w));
    }

    float a[8];
    #pragma unroll
    for (int k = 0; k < 4; k++) {
        float2 f0 = __half22float2(h0[k]);
        float2 f1 = __half22float2(h1[k]);
        a[2 * k]     = f0.x + f1.x;
        a[2 * k + 1] = f0.y + f1.y;
    }

    // lane pair exchange -> x[16] = the 16 inputs of bt-slice (lane>>1)
    int hi = lane & 1;
    float x[16];
    #pragma unroll
    for (int i = 0; i < 8; i++) {
        float other = __shfl_xor_sync(0xffffffffu, a[i], 1);
        x[i]     = hi ? other : a[i];
        x[8 + i] = hi ? a[i]  : other;
    }

    // even lane -> hidden 0..15, odd -> 16..31; weights via LDS.128
    const float4* sW1f4 = reinterpret_cast<const float4*>(sW1);
    int jb4 = hi ? 4 : 0;   // float4 offset within a 8-float4 row
    float acc[16];
    #pragma unroll
    for (int j = 0; j < 16; j++) acc[j] = sb1[hi * 16 + j];
    #pragma unroll
    for (int c = 0; c < 16; c++) {
        float xc = x[c];
        #pragma unroll
        for (int j4 = 0; j4 < 4; j4++) {
            float4 wv = sW1f4[c * 8 + jb4 + j4];
            acc[j4 * 4 + 0] = fmaf(xc, wv.x, acc[j4 * 4 + 0]);
            acc[j4 * 4 + 1] = fmaf(xc, wv.y, acc[j4 * 4 + 1]);
            acc[j4 * 4 + 2] = fmaf(xc, wv.z, acc[j4 * 4 + 2]);
            acc[j4 * 4 + 3] = fmaf(xc, wv.w, acc[j4 * 4 + 3]);
        }
    }
    float partial = 0.f;
    #pragma unroll
    for (int j = 0; j < 16; j++)
        partial = fmaf(fmaxf(acc[j], 0.f), sw2[hi * 16 + j], partial);
    partial += __shfl_xor_sync(0xffffffffu, partial, 1);
    if (!hi) g_s[n * 16 + (lane >> 1)] = partial;
}

// agg2 + b2 + tconv1 -> g_v[b][n]
__global__ void k_agg2(const float* __restrict__ b2,
                       const float* __restrict__ tw1,
                       const float* __restrict__ tb1) {
    int gt = blockIdx.x * blockDim.x + threadIdx.x;  // 1250*128 = N*16
    int n = gt >> 4;
    int l = gt & 15;
    int beg = g_rowptr[n], end = g_rowptr[n + 1];
    float acc = 0.f;
    int e = beg;
    for (; e + 1 < end; e += 2)
        acc += g_s[g_col[e] * 16 + l] + g_s[g_col[e + 1] * 16 + l];
    if (e < end) acc += g_s[g_col[e] * 16 + l];
    int b = l >> 3;
    int t = l & 7;
    float val = (acc + b2[0]) * tw1[t];
    val += __shfl_down_sync(0xffffffffu, val, 4);
    val += __shfl_down_sync(0xffffffffu, val, 2);
    val += __shfl_down_sync(0xffffffffu, val, 1);
    if (t == 0) g_v[b * N_NODES + n] = val + tb1[0];
}

__device__ __forceinline__ float bred(float val, float* red32) {
    int lane = threadIdx.x & 31, w = threadIdx.x >> 5;
    val += __shfl_down_sync(0xffffffffu, val, 16);
    val += __shfl_down_sync(0xffffffffu, val, 8);
    val += __shfl_down_sync(0xffffffffu, val, 4);
    val += __shfl_down_sync(0xffffffffu, val, 2);
    val += __shfl_down_sync(0xffffffffu, val, 1);
    if (lane == 0) red32[w] = val;
    __syncthreads();
    if (w == 0) {
        float x = red32[lane];
        x += __shfl_down_sync(0xffffffffu, x, 16);
        x += __shfl_down_sync(0xffffffffu, x, 8);
        x += __shfl_down_sync(0xffffffffu, x, 4);
        x += __shfl_down_sync(0xffffffffu, x, 2);
        x += __shfl_down_sync(0xffffffffu, x, 1);
        if (lane == 0) red32[0] = x;
    }
    __syncthreads();
    float r = red32[0];
    __syncthreads();
    return r;
}

// LN1 -> affine -> LN2, v cached in smem; writes g_z. One block per batch.
__global__ void __launch_bounds__(1024) k_ln(
        const float* __restrict__ ln1g, const float* __restrict__ ln1b,
        const float* __restrict__ tw2,  const float* __restrict__ tb2,
        const float* __restrict__ ln2g, const float* __restrict__ ln2b) {
    __shared__ float zv[N_NODES];   // 40000 B: holds v, then y2
    __shared__ float red32[32];
    int b = blockIdx.x;
    int tid = threadIdx.x;
    const float* v = g_v + b * N_NODES;
    float w2v = tw2[0], bb2 = tb2[0];

    float s = 0.f;
    for (int i = tid; i < N_NODES; i += 1024) { float x = v[i]; zv[i] = x; s += x; }
    float mu1 = bred(s, red32) * (1.f / N_NODES);
    s = 0.f;
    for (int i = tid; i < N_NODES; i += 1024) { float d = zv[i] - mu1; s += d * d; }
    float inv1 = rsqrtf(bred(s, red32) * (1.f / N_NODES) + EPS);
    s = 0.f;
    for (int i = tid; i < N_NODES; i += 1024) {
        float y2 = ((zv[i] - mu1) * inv1 * ln1g[i] + ln1b[i]) * w2v + bb2;
        zv[i] = y2;      // safe: each thread overwrites its own element
        s += y2;
    }
    float mu2 = bred(s, red32) * (1.f / N_NODES);
    s = 0.f;
    for (int i = tid; i < N_NODES; i += 1024) { float d = zv[i] - mu2; s += d * d; }
    float inv2 = rsqrtf(bred(s, red32) * (1.f / N_NODES) + EPS);
    for (int i = tid; i < N_NODES; i += 1024)
        g_z[b * N_NODES + i] = (zv[i] - mu2) * inv2 * ln2g[i] + ln2b[i];
}

// fc conv: one block per (class, batch)
__global__ void k_fc(const float* __restrict__ fc_w,
                     const float* __restrict__ fc_b,
                     float* __restrict__ out) {
    __shared__ float red32[32];
    int c = blockIdx.x, b = blockIdx.y;
    int tid = threadIdx.x;
    const float* z = g_z + b * N_NODES + c;
    float s = 0.f;
    for (int k = tid; k < KW; k += 256) s = fmaf(z[k], fc_w[k], s);
    int lane = tid & 31, w = tid >> 5;
    s += __shfl_down_sync(0xffffffffu, s, 16);
    s += __shfl_down_sync(0xffffffffu, s, 8);
    s += __shfl_down_sync(0xffffffffu, s, 4);
    s += __shfl_down_sync(0xffffffffu, s, 2);
    s += __shfl_down_sync(0xffffffffu, s, 1);
    if (lane == 0) red32[w] = s;
    __syncthreads();
    if (tid == 0) {
        float a = 0.f;
        #pragma unroll
        for (int i = 0; i < 8; i++) a += red32[i];
        out[b * NCLASS + c] = a + fc_b[0];
    }
}

// ---------------- launch ----------------
extern "C" void kernel_launch(void* const* d_in, const int* in_sizes, int n_in,
                              void* d_out, int out_size) {
    const float* features = (const float*)d_in[0];
    const int*   src      = (const int*)d_in[1];
    const int*   dst      = (const int*)d_in[2];
    const float* W1       = (const float*)d_in[3];
    const float* b1       = (const float*)d_in[4];
    const float* W2       = (const float*)d_in[5];
    const float* b2       = (const float*)d_in[6];
    const float* tconv1_w = (const float*)d_in[7];
    const float* tconv1_b = (const float*)d_in[8];
    const float* ln1_g    = (const float*)d_in[9];
    const float* ln1_b    = (const float*)d_in[10];
    const float* tconv2_w = (const float*)d_in[11];
    const float* tconv2_b = (const float*)d_in[12];
    const float* ln2_g    = (const float*)d_in[13];
    const float* ln2_b    = (const float*)d_in[14];
    const float* fc_w     = (const float*)d_in[15];
    const float* fc_b     = (const float*)d_in[16];
    float* out = (float*)d_out;

    k_pre<<<470, 256>>>(features, dst);            // transpose + hist
    k_scan<<<1, 1024>>>();
    k_fill<<<157, 256>>>(src, dst);
    k_aggmlp<<<1250, 256>>>(W1, b1, W2);
    k_agg2<<<1250, 128>>>(b2, tconv1_w, tconv1_b);
    k_ln<<<BATCH, 1024>>>(ln1_g, ln1_b, tconv2_w, tconv2_b, ln2_g, ln2_b);
    k_fc<<<dim3(NCLASS, BATCH), 256>>>(fc_w, fc_b, out);
}